// round 1
// baseline (speedup 1.0000x reference)
#include <cuda_runtime.h>
#include <math.h>

// Problem constants
#define TTOK 8192          // B*S tokens
#define NEXP 8             // experts
#define TOPK 2
#define DIM  1024          // n_embd
#define FFD  2048          // d_ffn per expert
#define W1LD (FFD*NEXP)    // 16384, row stride of w1 [D, FF*E]

// ---------------- device scratch (static; no allocation in kernel_launch) ----
__device__ int   g_cnt[NEXP];                       // tokens per expert
__device__ int   g_list[NEXP * TTOK];               // tokslot = t*2+k, grouped per expert
__device__ float g_wt[TTOK * TOPK];                 // normalized top-k weight per (t,k)
__device__ float g_h[(size_t)TTOK * TOPK * FFD];    // gelu(x@w1) rows, indexed by tokslot (134 MB)
__device__ float g_zpart[TTOK / 8];                 // per-block z-loss partials (1024)
__device__ float g_ppart[(TTOK / 8) * NEXP];        // per-block prob-sum partials

// ---------------- init: zero output tensor + expert counters ----------------
__global__ void moe_init_kernel(float* __restrict__ out) {
    long i = (long)blockIdx.x * blockDim.x + threadIdx.x;
    long n4 = (long)TTOK * DIM / 4;
    float4 z = make_float4(0.f, 0.f, 0.f, 0.f);
    for (long j = i; j < n4; j += (long)gridDim.x * blockDim.x)
        reinterpret_cast<float4*>(out)[j] = z;
    if (i < NEXP) g_cnt[(int)i] = 0;
}

// ---------------- routing: logits, softmax, top-2, lists, loss partials -----
// one warp per token, 8 warps per block, 1024 blocks
__global__ void routing_kernel(const float* __restrict__ x,
                               const float* __restrict__ rw) {
    __shared__ float s_rw[NEXP * DIM];    // 32 KB
    __shared__ float s_z[8];
    __shared__ float s_p[8][NEXP];

    for (int i = threadIdx.x; i < NEXP * DIM; i += blockDim.x) s_rw[i] = rw[i];
    __syncthreads();

    int warp = threadIdx.x >> 5;
    int lane = threadIdx.x & 31;
    int t = blockIdx.x * 8 + warp;

    float acc[NEXP];
#pragma unroll
    for (int e = 0; e < NEXP; e++) acc[e] = 0.f;

    const float* xp = x + (size_t)t * DIM;
    for (int i = lane; i < DIM; i += 32) {
        float xv = xp[i];
#pragma unroll
        for (int e = 0; e < NEXP; e++) acc[e] = fmaf(xv, s_rw[e * DIM + i], acc[e]);
    }
#pragma unroll
    for (int e = 0; e < NEXP; e++) {
#pragma unroll
        for (int o = 16; o > 0; o >>= 1)
            acc[e] += __shfl_xor_sync(0xffffffffu, acc[e], o);
    }

    if (lane == 0) {
        float m = acc[0];
#pragma unroll
        for (int e = 1; e < NEXP; e++) m = fmaxf(m, acc[e]);
        float p[NEXP];
        float s = 0.f;
#pragma unroll
        for (int e = 0; e < NEXP; e++) { p[e] = expf(acc[e] - m); s += p[e]; }
        float inv = 1.f / s;
#pragma unroll
        for (int e = 0; e < NEXP; e++) p[e] *= inv;

        // top-2, lowest-index wins on ties (matches jax.lax.top_k)
        int i1 = 0;
#pragma unroll
        for (int e = 1; e < NEXP; e++) if (p[e] > p[i1]) i1 = e;
        int i2 = (i1 == 0) ? 1 : 0;
#pragma unroll
        for (int e = 0; e < NEXP; e++) if (e != i1 && p[e] > p[i2]) i2 = e;

        float sw = p[i1] + p[i2];
        float wA = p[i1] / sw;
        float wB = p[i2] / sw;

        int pos1 = atomicAdd(&g_cnt[i1], 1);
        g_list[i1 * TTOK + pos1] = t * 2;
        int pos2 = atomicAdd(&g_cnt[i2], 1);
        g_list[i2 * TTOK + pos2] = t * 2 + 1;
        g_wt[t * 2 + 0] = wA;
        g_wt[t * 2 + 1] = wB;

        float lse = m + logf(s);
        s_z[warp] = lse * lse;
#pragma unroll
        for (int e = 0; e < NEXP; e++) s_p[warp][e] = p[e];
    }
    __syncthreads();
    if (threadIdx.x == 0) {
        float zz = 0.f;
#pragma unroll
        for (int w = 0; w < 8; w++) zz += s_z[w];
        g_zpart[blockIdx.x] = zz;
    }
    if (threadIdx.x < NEXP) {
        float pp = 0.f;
#pragma unroll
        for (int w = 0; w < 8; w++) pp += s_p[w][threadIdx.x];
        g_ppart[blockIdx.x * NEXP + threadIdx.x] = pp;
    }
}

// ---------------- GEMM1: h[tokslot] = gelu( x[tok] @ w1_e ) -----------------
// tiles 128x128x8, 256 threads, 8x8 microtile. grid = (64, FF/128=16, E)
__global__ void gemm1_kernel(const float* __restrict__ x,
                             const float* __restrict__ w1) {
    int e = blockIdx.z;
    int cnt = g_cnt[e];
    int m0 = blockIdx.x * 128;
    if (m0 >= cnt) return;
    int n0 = blockIdx.y * 128;

    __shared__ __align__(16) float As[8][128];
    __shared__ __align__(16) float Bs[8][128];

    int tid = threadIdx.x;
    int arow = tid >> 1;
    int acol = (tid & 1) * 4;
    int arow_g = m0 + arow;
    int aidx = (arow_g < cnt) ? arow_g : (cnt - 1);
    int toksA = g_list[e * TTOK + aidx];
    const float* aptr = x + (size_t)(toksA >> 1) * DIM + acol;

    int brow = tid >> 5;
    int bcol = (tid & 31) * 4;
    const float* bptr = w1 + (size_t)brow * W1LD + e * FFD + n0 + bcol;

    int tx = tid & 15, ty = tid >> 4;

    float acc[8][8];
#pragma unroll
    for (int i = 0; i < 8; i++)
#pragma unroll
        for (int j = 0; j < 8; j++) acc[i][j] = 0.f;

    for (int k0 = 0; k0 < DIM; k0 += 8) {
        float4 av = *reinterpret_cast<const float4*>(aptr + k0);
        float4 bv = *reinterpret_cast<const float4*>(bptr + (size_t)k0 * W1LD);
        __syncthreads();
        As[acol + 0][arow] = av.x;
        As[acol + 1][arow] = av.y;
        As[acol + 2][arow] = av.z;
        As[acol + 3][arow] = av.w;
        *reinterpret_cast<float4*>(&Bs[brow][bcol]) = bv;
        __syncthreads();
#pragma unroll
        for (int kk = 0; kk < 8; kk++) {
            float a[8], b[8];
            *reinterpret_cast<float4*>(&a[0]) = *reinterpret_cast<const float4*>(&As[kk][ty * 4]);
            *reinterpret_cast<float4*>(&a[4]) = *reinterpret_cast<const float4*>(&As[kk][64 + ty * 4]);
            *reinterpret_cast<float4*>(&b[0]) = *reinterpret_cast<const float4*>(&Bs[kk][tx * 4]);
            *reinterpret_cast<float4*>(&b[4]) = *reinterpret_cast<const float4*>(&Bs[kk][64 + tx * 4]);
#pragma unroll
            for (int i = 0; i < 8; i++)
#pragma unroll
                for (int j = 0; j < 8; j++) acc[i][j] = fmaf(a[i], b[j], acc[i][j]);
        }
    }

#pragma unroll
    for (int i = 0; i < 8; i++) {
        int rloc = (i < 4) ? (ty * 4 + i) : (64 + ty * 4 + i - 4);
        int rm = m0 + rloc;
        if (rm >= cnt) continue;
        int toks = g_list[e * TTOK + rm];
        float* hp = g_h + (size_t)toks * FFD + n0;
#pragma unroll
        for (int j = 0; j < 8; j++) {
            int cn = (j < 4) ? (tx * 4 + j) : (64 + tx * 4 + j - 4);
            float v = acc[i][j];
            hp[cn] = 0.5f * v * (1.0f + erff(v * 0.70710678118654752f));  // exact gelu
        }
    }
}

// ---------------- GEMM2: out[tok] += wt * ( h[tokslot] @ w2_e ) -------------
// grid = (64, D/128=8, E). Exactly 2 contributions per out element -> atomicAdd
// is bitwise-deterministic over zeroed output.
__global__ void gemm2_kernel(const float* __restrict__ w2,
                             float* __restrict__ out) {
    int e = blockIdx.z;
    int cnt = g_cnt[e];
    int m0 = blockIdx.x * 128;
    if (m0 >= cnt) return;
    int n0 = blockIdx.y * 128;

    __shared__ __align__(16) float As[8][128];
    __shared__ __align__(16) float Bs[8][128];

    int tid = threadIdx.x;
    int arow = tid >> 1;
    int acol = (tid & 1) * 4;
    int arow_g = m0 + arow;
    int aidx = (arow_g < cnt) ? arow_g : (cnt - 1);
    int toksA = g_list[e * TTOK + aidx];
    const float* aptr = g_h + (size_t)toksA * FFD + acol;

    int brow = tid >> 5;
    int bcol = (tid & 31) * 4;
    const float* bptr = w2 + ((size_t)e * FFD + brow) * DIM + n0 + bcol;

    int tx = tid & 15, ty = tid >> 4;

    float acc[8][8];
#pragma unroll
    for (int i = 0; i < 8; i++)
#pragma unroll
        for (int j = 0; j < 8; j++) acc[i][j] = 0.f;

    for (int k0 = 0; k0 < FFD; k0 += 8) {
        float4 av = *reinterpret_cast<const float4*>(aptr + k0);
        float4 bv = *reinterpret_cast<const float4*>(bptr + (size_t)k0 * DIM);
        __syncthreads();
        As[acol + 0][arow] = av.x;
        As[acol + 1][arow] = av.y;
        As[acol + 2][arow] = av.z;
        As[acol + 3][arow] = av.w;
        *reinterpret_cast<float4*>(&Bs[brow][bcol]) = bv;
        __syncthreads();
#pragma unroll
        for (int kk = 0; kk < 8; kk++) {
            float a[8], b[8];
            *reinterpret_cast<float4*>(&a[0]) = *reinterpret_cast<const float4*>(&As[kk][ty * 4]);
            *reinterpret_cast<float4*>(&a[4]) = *reinterpret_cast<const float4*>(&As[kk][64 + ty * 4]);
            *reinterpret_cast<float4*>(&b[0]) = *reinterpret_cast<const float4*>(&Bs[kk][tx * 4]);
            *reinterpret_cast<float4*>(&b[4]) = *reinterpret_cast<const float4*>(&Bs[kk][64 + tx * 4]);
#pragma unroll
            for (int i = 0; i < 8; i++)
#pragma unroll
                for (int j = 0; j < 8; j++) acc[i][j] = fmaf(a[i], b[j], acc[i][j]);
        }
    }

#pragma unroll
    for (int i = 0; i < 8; i++) {
        int rloc = (i < 4) ? (ty * 4 + i) : (64 + ty * 4 + i - 4);
        int rm = m0 + rloc;
        if (rm >= cnt) continue;
        int toks = g_list[e * TTOK + rm];
        float w = g_wt[toks];
        float* op = out + (size_t)(toks >> 1) * DIM + n0;
#pragma unroll
        for (int j = 0; j < 8; j++) {
            int cn = (j < 4) ? (tx * 4 + j) : (64 + tx * 4 + j - 4);
            atomicAdd(&op[cn], w * acc[i][j]);
        }
    }
}

// ---------------- finalize: loss scalars (fixed-order reductions) -----------
__global__ void finalize_kernel(float* __restrict__ out) {
    __shared__ float s_p[NEXP];
    __shared__ float s_z;
    int tid = threadIdx.x;
    if (tid < NEXP) {
        float s = 0.f;
        for (int b = 0; b < TTOK / 8; b++) s += g_ppart[b * NEXP + tid];
        s_p[tid] = s;
    }
    if (tid == 8) {
        float s = 0.f;
        for (int b = 0; b < TTOK / 8; b++) s += g_zpart[b];
        s_z = s;
    }
    __syncthreads();
    if (tid == 0) {
        float z = s_z / (float)TTOK;
        float lb = 0.f;
        for (int e = 0; e < NEXP; e++)
            lb += ((float)g_cnt[e] / (float)(TTOK * TOPK)) * (s_p[e] / (float)TTOK);
        lb *= (float)NEXP;
        out[(size_t)TTOK * DIM + 0] = z;
        out[(size_t)TTOK * DIM + 1] = lb;
    }
}

// ---------------- launch ----------------------------------------------------
extern "C" void kernel_launch(void* const* d_in, const int* in_sizes, int n_in,
                              void* d_out, int out_size) {
    const float* x  = (const float*)d_in[0];   // [T, D]
    const float* rw = (const float*)d_in[1];   // [E, D]
    const float* w1 = (const float*)d_in[2];   // [D, FF*E]
    const float* w2 = (const float*)d_in[3];   // [FF*E, D]
    float* out = (float*)d_out;                // [T*D + 2]

    moe_init_kernel<<<2048, 256>>>(out);
    routing_kernel<<<TTOK / 8, 256>>>(x, rw);

    dim3 g1(TTOK / 128, FFD / 128, NEXP);      // (64,16,8); blocks beyond cnt exit
    gemm1_kernel<<<g1, 256>>>(x, w1);

    dim3 g2(TTOK / 128, DIM / 128, NEXP);      // (64,8,8)
    gemm2_kernel<<<g2, 256>>>(w2, out);

    finalize_kernel<<<1, 32>>>(out);
}

// round 3
// speedup vs baseline: 2.4251x; 2.4251x over previous
#include <cuda_runtime.h>
#include <math.h>
#include <stdint.h>

// ---------------- problem constants ----------------
#define TTOK 8192
#define NEXP 8
#define TOPK 2
#define DIM  1024          // K of GEMM1, N of GEMM2
#define FFD  2048          // N of GEMM1, K of GEMM2

// ---------------- GEMM tiling ----------------
#define BM 128
#define BN 128
#define BK 16
#define NS 4                               // cp.async stages
#define STAGE_FLOATS (BM*BK + BN*BK)       // 4096 floats = 16KB
#define SMEM_BYTES (NS * STAGE_FLOATS * 4) // 64KB

// kperm within each 16-float chunk: thread fragment k-values {c,c+4,c+8,c+12} -> contiguous
__host__ __device__ __forceinline__ int kperm(int k) {
    return (k & ~15) | ((k & 3) << 2) | ((k >> 2) & 3);
}

// ---------------- device scratch ----------------
__device__ int   g_cnt[NEXP];
__device__ int   g_list[NEXP * TTOK];
__device__ float g_wt[TTOK * TOPK];
__device__ float g_xp[(size_t)TTOK * DIM];          // x, kperm + tf32      (33 MB)
__device__ float g_h[(size_t)TTOK * TOPK * FFD];    // gelu out, kperm tf32 (134 MB)
__device__ float g_y[(size_t)TTOK * TOPK * DIM];    // per-slot outputs     (67 MB)
__device__ float g_w1t[(size_t)NEXP * FFD * DIM];   // w1^T [E*FF][perm(D)] (64 MB)
__device__ float g_w2t[(size_t)NEXP * DIM * FFD];   // w2^T [E][D][perm(FF)](64 MB)
__device__ float g_zpart[TTOK / 8];
__device__ float g_ppart[(TTOK / 8) * NEXP];

// ---------------- helpers ----------------
__device__ __forceinline__ uint32_t smem_u32(const void* p) {
    uint32_t a;
    asm("{ .reg .u64 t; cvta.to.shared.u64 t, %1; cvt.u32.u64 %0, t; }" : "=r"(a) : "l"(p));
    return a;
}
__device__ __forceinline__ uint32_t f2tf32(float f) {
    uint32_t r;
    asm("cvt.rna.tf32.f32 %0, %1;" : "=r"(r) : "f"(f));
    return r;
}
__device__ __forceinline__ void cp16(uint32_t saddr, const void* g) {
    asm volatile("cp.async.cg.shared.global [%0], [%1], 16;" :: "r"(saddr), "l"(g) : "memory");
}
#define CP_COMMIT() asm volatile("cp.async.commit_group;" ::: "memory")
#define CP_WAIT2()  asm volatile("cp.async.wait_group 2;" ::: "memory")

__device__ __forceinline__ void mma_tf32(float* c, uint32_t a0, uint32_t a1, uint32_t a2,
                                         uint32_t a3, uint32_t b0, uint32_t b1) {
    asm volatile(
        "mma.sync.aligned.m16n8k8.row.col.f32.tf32.tf32.f32 "
        "{%0,%1,%2,%3}, {%4,%5,%6,%7}, {%8,%9}, {%0,%1,%2,%3};"
        : "+f"(c[0]), "+f"(c[1]), "+f"(c[2]), "+f"(c[3])
        : "r"(a0), "r"(a1), "r"(a2), "r"(a3), "r"(b0), "r"(b1));
}

__device__ __forceinline__ float gelu_exact(float v) {
    return 0.5f * v * (1.0f + erff(v * 0.70710678118654752f));
}

// ---------------- init ----------------
__global__ void init_kernel() {
    if (threadIdx.x < NEXP) g_cnt[threadIdx.x] = 0;
}

// ---------------- pre-pass: permute x, transpose+permute weights (all tf32) --
__global__ void permute_x_kernel(const float* __restrict__ x) {
    size_t i = (size_t)blockIdx.x * blockDim.x + threadIdx.x;
    size_t n = (size_t)TTOK * DIM;
    for (size_t j = i; j < n; j += (size_t)gridDim.x * blockDim.x) {
        int t = (int)(j / DIM), d = (int)(j % DIM);
        g_xp[(size_t)t * DIM + kperm(d)] = __uint_as_float(f2tf32(x[j]));
    }
}
// w1 [D][E*FF] -> g_w1t [E*FF][perm(D)]
__global__ void transpose_w1_kernel(const float* __restrict__ w1) {
    __shared__ float t[32][33];
    int bx = blockIdx.x * 32;   // N (E*FF)
    int by = blockIdx.y * 32;   // K (D)
    int x = threadIdx.x, y = threadIdx.y;
#pragma unroll
    for (int i = 0; i < 32; i += 8)
        t[y + i][x] = w1[(size_t)(by + y + i) * (NEXP * FFD) + bx + x];
    __syncthreads();
#pragma unroll
    for (int i = 0; i < 32; i += 8)
        g_w1t[(size_t)(bx + y + i) * DIM + kperm(by + x)] =
            __uint_as_float(f2tf32(t[x][y + i]));
}
// w2 per-expert [FF][D] -> g_w2t[e] [D][perm(FF)]
__global__ void transpose_w2_kernel(const float* __restrict__ w2) {
    __shared__ float t[32][33];
    int e = blockIdx.z;
    const float* in = w2 + (size_t)e * FFD * DIM;
    float* out = g_w2t + (size_t)e * DIM * FFD;
    int bx = blockIdx.x * 32;   // D
    int by = blockIdx.y * 32;   // FF
    int x = threadIdx.x, y = threadIdx.y;
#pragma unroll
    for (int i = 0; i < 32; i += 8)
        t[y + i][x] = in[(size_t)(by + y + i) * DIM + bx + x];
    __syncthreads();
#pragma unroll
    for (int i = 0; i < 32; i += 8)
        out[(size_t)(bx + y + i) * FFD + kperm(by + x)] =
            __uint_as_float(f2tf32(t[x][y + i]));
}

// ---------------- routing ----------------
__global__ void routing_kernel(const float* __restrict__ x,
                               const float* __restrict__ rw) {
    __shared__ float s_rw[NEXP * DIM];
    __shared__ float s_z[8];
    __shared__ float s_p[8][NEXP];

    for (int i = threadIdx.x; i < NEXP * DIM; i += blockDim.x) s_rw[i] = rw[i];
    __syncthreads();

    int warp = threadIdx.x >> 5;
    int lane = threadIdx.x & 31;
    int t = blockIdx.x * 8 + warp;

    float acc[NEXP];
#pragma unroll
    for (int e = 0; e < NEXP; e++) acc[e] = 0.f;
    const float* xp = x + (size_t)t * DIM;
    for (int i = lane; i < DIM; i += 32) {
        float xv = xp[i];
#pragma unroll
        for (int e = 0; e < NEXP; e++) acc[e] = fmaf(xv, s_rw[e * DIM + i], acc[e]);
    }
#pragma unroll
    for (int e = 0; e < NEXP; e++) {
#pragma unroll
        for (int o = 16; o > 0; o >>= 1)
            acc[e] += __shfl_xor_sync(0xffffffffu, acc[e], o);
    }
    if (lane == 0) {
        float m = acc[0];
#pragma unroll
        for (int e = 1; e < NEXP; e++) m = fmaxf(m, acc[e]);
        float p[NEXP]; float s = 0.f;
#pragma unroll
        for (int e = 0; e < NEXP; e++) { p[e] = expf(acc[e] - m); s += p[e]; }
        float inv = 1.f / s;
#pragma unroll
        for (int e = 0; e < NEXP; e++) p[e] *= inv;
        int i1 = 0;
#pragma unroll
        for (int e = 1; e < NEXP; e++) if (p[e] > p[i1]) i1 = e;
        int i2 = (i1 == 0) ? 1 : 0;
#pragma unroll
        for (int e = 0; e < NEXP; e++) if (e != i1 && p[e] > p[i2]) i2 = e;
        float sw = p[i1] + p[i2];
        int pos1 = atomicAdd(&g_cnt[i1], 1);
        g_list[i1 * TTOK + pos1] = t * 2;
        int pos2 = atomicAdd(&g_cnt[i2], 1);
        g_list[i2 * TTOK + pos2] = t * 2 + 1;
        g_wt[t * 2 + 0] = p[i1] / sw;
        g_wt[t * 2 + 1] = p[i2] / sw;
        float lse = m + logf(s);
        s_z[warp] = lse * lse;
#pragma unroll
        for (int e = 0; e < NEXP; e++) s_p[warp][e] = p[e];
    }
    __syncthreads();
    if (threadIdx.x == 0) {
        float zz = 0.f;
#pragma unroll
        for (int w = 0; w < 8; w++) zz += s_z[w];
        g_zpart[blockIdx.x] = zz;
    }
    if (threadIdx.x < NEXP) {
        float pp = 0.f;
#pragma unroll
        for (int w = 0; w < 8; w++) pp += s_p[w][threadIdx.x];
        g_ppart[blockIdx.x * NEXP + threadIdx.x] = pp;
    }
}

// ---------------- tf32 mma.sync GEMM core (shared by both gemms) ------------
// Computes acc[4][4][4] for a 128x128 tile. agp/bgp are per-thread row base
// pointers (thread handles row tid>>1, 32B segment tid&1 of each 64B chunk).
struct GemmCore {
    float acc[4][4][4];

    __device__ __forceinline__ void run(const float* agp, const float* bgp,
                                        float* smem, int NC, int tid) {
        int lane = tid & 31;
        int wid = tid >> 5;
        int wm = (wid & 1) * 64;
        int wn = (wid >> 1) * 32;

#pragma unroll
        for (int i = 0; i < 4; i++)
#pragma unroll
            for (int j = 0; j < 4; j++)
#pragma unroll
                for (int r = 0; r < 4; r++) acc[i][j][r] = 0.f;

        int crow = tid >> 1;
        int cseg = (tid & 1) * 8;   // floats

        // prologue: stages 0..NS-2
#pragma unroll
        for (int c = 0; c < NS - 1; c++) {
            float* As = smem + (c & (NS - 1)) * STAGE_FLOATS;
            float* Bs = As + BM * BK;
            uint32_t sa = smem_u32(As + crow * BK + cseg);
            const float* ga = agp + c * BK + cseg;
            cp16(sa, ga); cp16(sa + 16, ga + 4);
            uint32_t sbb = smem_u32(Bs + crow * BK + cseg);
            const float* gb = bgp + c * BK + cseg;
            cp16(sbb, gb); cp16(sbb + 16, gb + 4);
            CP_COMMIT();
        }

        for (int c = 0; c < NC; c++) {
            CP_WAIT2();
            __syncthreads();
            // issue chunk c+NS-1 into stage (c-1)&mask (done being read)
            int cn = c + NS - 1;
            if (cn < NC) {
                float* As = smem + (cn & (NS - 1)) * STAGE_FLOATS;
                float* Bs = As + BM * BK;
                uint32_t sa = smem_u32(As + crow * BK + cseg);
                const float* ga = agp + cn * BK + cseg;
                cp16(sa, ga); cp16(sa + 16, ga + 4);
                uint32_t sbb = smem_u32(Bs + crow * BK + cseg);
                const float* gb = bgp + cn * BK + cseg;
                cp16(sbb, gb); cp16(sbb + 16, gb + 4);
            }
            CP_COMMIT();

            // compute chunk c
            float* As = smem + (c & (NS - 1)) * STAGE_FLOATS;
            float* Bs = As + BM * BK;
            uint32_t bf[4][4];
#pragma unroll
            for (int nt = 0; nt < 4; nt++) {
                const float4 v = *reinterpret_cast<const float4*>(
                    Bs + (wn + nt * 8 + (lane >> 2)) * BK + (lane & 3) * 4);
                bf[nt][0] = __float_as_uint(v.x);
                bf[nt][1] = __float_as_uint(v.y);
                bf[nt][2] = __float_as_uint(v.z);
                bf[nt][3] = __float_as_uint(v.w);
            }
#pragma unroll
            for (int mt = 0; mt < 4; mt++) {
                int r = wm + mt * 16 + (lane >> 2);
                const float4 lo = *reinterpret_cast<const float4*>(
                    As + r * BK + (lane & 3) * 4);
                const float4 hi = *reinterpret_cast<const float4*>(
                    As + (r + 8) * BK + (lane & 3) * 4);
#pragma unroll
                for (int nt = 0; nt < 4; nt++) {
                    mma_tf32(acc[mt][nt],
                             __float_as_uint(lo.x), __float_as_uint(hi.x),
                             __float_as_uint(lo.y), __float_as_uint(hi.y),
                             bf[nt][0], bf[nt][1]);
                    mma_tf32(acc[mt][nt],
                             __float_as_uint(lo.z), __float_as_uint(hi.z),
                             __float_as_uint(lo.w), __float_as_uint(hi.w),
                             bf[nt][2], bf[nt][3]);
                }
            }
        }
    }
};

// GEMM1: h[slot][perm] = tf32(gelu( x[tok] @ w1_e ))   M=cnt[e], N=FFD, K=DIM
__global__ void __launch_bounds__(256, 1) gemm1_mma() {
    int e = blockIdx.z;
    int cnt = g_cnt[e];
    int m0 = blockIdx.x * BM;
    if (m0 >= cnt) return;
    int n0 = blockIdx.y * BN;

    extern __shared__ __align__(16) float smem[];
    int tid = threadIdx.x;

    int crow = tid >> 1;
    int aidx = (m0 + crow < cnt) ? (m0 + crow) : (cnt - 1);
    int atoks = g_list[e * TTOK + aidx];
    const float* agp = g_xp + (size_t)(atoks >> 1) * DIM;
    const float* bgp = g_w1t + ((size_t)e * FFD + n0 + crow) * DIM;

    GemmCore core;
    core.run(agp, bgp, smem, DIM / BK, tid);

    // epilogue: gelu + tf32 + permuted scatter into g_h
    int lane = tid & 31;
    int wid = tid >> 5;
    int wm = (wid & 1) * 64;
    int wn = (wid >> 1) * 32;
#pragma unroll
    for (int mt = 0; mt < 4; mt++) {
        int rloc = wm + mt * 16 + (lane >> 2);
#pragma unroll
        for (int half = 0; half < 2; half++) {
            int rm = m0 + rloc + half * 8;
            if (rm >= cnt) continue;
            int slot = g_list[e * TTOK + rm];
            float* hp = g_h + (size_t)slot * FFD;
#pragma unroll
            for (int nt = 0; nt < 4; nt++) {
#pragma unroll
                for (int j = 0; j < 2; j++) {
                    int nn = n0 + wn + nt * 8 + (lane & 3) * 2 + j;
                    float v = core.acc[mt][nt][half * 2 + j];
                    hp[kperm(nn)] = __uint_as_float(f2tf32(gelu_exact(v)));
                }
            }
        }
    }
}

// GEMM2: y[slot] = wt * ( h[slot] @ w2_e )   M=cnt[e], N=DIM, K=FFD
__global__ void __launch_bounds__(256, 1) gemm2_mma() {
    int e = blockIdx.z;
    int cnt = g_cnt[e];
    int m0 = blockIdx.x * BM;
    if (m0 >= cnt) return;
    int n0 = blockIdx.y * BN;

    extern __shared__ __align__(16) float smem[];
    int tid = threadIdx.x;

    int crow = tid >> 1;
    int aidx = (m0 + crow < cnt) ? (m0 + crow) : (cnt - 1);
    int aslot = g_list[e * TTOK + aidx];
    const float* agp = g_h + (size_t)aslot * FFD;
    const float* bgp = g_w2t + ((size_t)e * DIM + n0 + crow) * FFD;

    GemmCore core;
    core.run(agp, bgp, smem, FFD / BK, tid);

    int lane = tid & 31;
    int wid = tid >> 5;
    int wm = (wid & 1) * 64;
    int wn = (wid >> 1) * 32;
#pragma unroll
    for (int mt = 0; mt < 4; mt++) {
        int rloc = wm + mt * 16 + (lane >> 2);
#pragma unroll
        for (int half = 0; half < 2; half++) {
            int rm = m0 + rloc + half * 8;
            if (rm >= cnt) continue;
            int slot = g_list[e * TTOK + rm];
            float wv = g_wt[slot];
            float* yp = g_y + (size_t)slot * DIM + n0;
#pragma unroll
            for (int nt = 0; nt < 4; nt++) {
                float2 v;
                v.x = wv * core.acc[mt][nt][half * 2 + 0];
                v.y = wv * core.acc[mt][nt][half * 2 + 1];
                *reinterpret_cast<float2*>(yp + wn + nt * 8 + (lane & 3) * 2) = v;
            }
        }
    }
}

// ---------------- combine: out[t] = y[2t] + y[2t+1] ----------------
__global__ void combine_kernel(float* __restrict__ out) {
    size_t i = (size_t)blockIdx.x * blockDim.x + threadIdx.x;
    size_t n4 = (size_t)TTOK * DIM / 4;
    const float4* y4 = reinterpret_cast<const float4*>(g_y);
    for (size_t j = i; j < n4; j += (size_t)gridDim.x * blockDim.x) {
        size_t t = j / (DIM / 4);
        size_t d = j % (DIM / 4);
        float4 a = y4[(2 * t) * (DIM / 4) + d];
        float4 b = y4[(2 * t + 1) * (DIM / 4) + d];
        float4 o;
        o.x = a.x + b.x; o.y = a.y + b.y; o.z = a.z + b.z; o.w = a.w + b.w;
        reinterpret_cast<float4*>(out)[j] = o;
    }
}

// ---------------- finalize losses ----------------
__global__ void finalize_kernel(float* __restrict__ out) {
    __shared__ float s_p[NEXP];
    __shared__ float s_z;
    int tid = threadIdx.x;
    if (tid < NEXP) {
        float s = 0.f;
        for (int b = 0; b < TTOK / 8; b++) s += g_ppart[b * NEXP + tid];
        s_p[tid] = s;
    }
    if (tid == 8) {
        float s = 0.f;
        for (int b = 0; b < TTOK / 8; b++) s += g_zpart[b];
        s_z = s;
    }
    __syncthreads();
    if (tid == 0) {
        float z = s_z / (float)TTOK;
        float lb = 0.f;
        for (int e = 0; e < NEXP; e++)
            lb += ((float)g_cnt[e] / (float)(TTOK * TOPK)) * (s_p[e] / (float)TTOK);
        lb *= (float)NEXP;
        out[(size_t)TTOK * DIM + 0] = z;
        out[(size_t)TTOK * DIM + 1] = lb;
    }
}

// ---------------- launch ----------------
extern "C" void kernel_launch(void* const* d_in, const int* in_sizes, int n_in,
                              void* d_out, int out_size) {
    const float* x  = (const float*)d_in[0];
    const float* rw = (const float*)d_in[1];
    const float* w1 = (const float*)d_in[2];
    const float* w2 = (const float*)d_in[3];
    float* out = (float*)d_out;

    cudaFuncSetAttribute(gemm1_mma, cudaFuncAttributeMaxDynamicSharedMemorySize, SMEM_BYTES);
    cudaFuncSetAttribute(gemm2_mma, cudaFuncAttributeMaxDynamicSharedMemorySize, SMEM_BYTES);

    init_kernel<<<1, 32>>>();
    permute_x_kernel<<<2048, 256>>>(x);
    transpose_w1_kernel<<<dim3(NEXP * FFD / 32, DIM / 32), dim3(32, 8)>>>(w1);
    transpose_w2_kernel<<<dim3(DIM / 32, FFD / 32, NEXP), dim3(32, 8)>>>(w2);
    routing_kernel<<<TTOK / 8, 256>>>(x, rw);

    gemm1_mma<<<dim3(TTOK / BM, FFD / BN, NEXP), 256, SMEM_BYTES>>>();
    gemm2_mma<<<dim3(TTOK / BM, DIM / BN, NEXP), 256, SMEM_BYTES>>>();

    combine_kernel<<<2048, 256>>>(out);
    finalize_kernel<<<1, 32>>>(out);
}